// round 17
// baseline (speedup 1.0000x reference)
#include <cuda_runtime.h>
#include <cstdint>

// SNN: x[B,5] -> L1(32) -> spike(dot>=2) -> L2(32) -> L3(16) -> L4(10) -> spike.
// R8 body (const-port W1, direct __ldg x, zero-fill + rare scatter, popc gate
// via setup kernel: sound bound, rel_err==0 across R3-R16), processing TWO
// rows per thread so each uniform LDCU weight load feeds both rows' FMAs.

__constant__ __align__(16) float cW1[160];
__device__ int g_minpop;

__global__ void setup_kernel(const float* __restrict__ W2) {
    int i = threadIdx.x;
    float mx = W2[i];
    #pragma unroll
    for (int j = 1; j < 32; j++) mx = fmaxf(mx, W2[j * 32 + i]);
    #pragma unroll
    for (int s = 16; s > 0; s >>= 1)
        mx = fmaxf(mx, __shfl_xor_sync(0xffffffffu, mx, s));
    if (i == 0) {
        int mp = 1;  // smallest popc whose bound popc*cmax could round to >= 2
        while (mp < 33 && (float)mp * mx < 1.99f) mp++;
        g_minpop = mp;
    }
}

// exact layers 2-4 (rare, ~1e-4 of rows); identical to R1-R16 validated code.
__device__ __noinline__ unsigned rare_path(unsigned mask1,
                                           const float* __restrict__ W2,
                                           const float* __restrict__ W3,
                                           const float* __restrict__ W4)
{
    unsigned mask2 = 0;
    #pragma unroll
    for (int jc = 0; jc < 32; jc += 8) {
        float acc[8] = {0, 0, 0, 0, 0, 0, 0, 0};
        unsigned mm = mask1;
        while (mm) {
            int i = __ffs(mm) - 1; mm &= mm - 1;
            #pragma unroll
            for (int j = 0; j < 8; j++) acc[j] += W2[(jc + j) * 32 + i];
        }
        #pragma unroll
        for (int j = 0; j < 8; j++)
            if (acc[j] >= 2.0f) mask2 |= 1u << (jc + j);
    }
    if (!mask2) return 0;

    unsigned mask3 = 0;
    #pragma unroll
    for (int jc = 0; jc < 16; jc += 8) {
        float acc[8] = {0, 0, 0, 0, 0, 0, 0, 0};
        unsigned mm = mask2;
        while (mm) {
            int i = __ffs(mm) - 1; mm &= mm - 1;
            #pragma unroll
            for (int j = 0; j < 8; j++) acc[j] += W3[(jc + j) * 32 + i];
        }
        #pragma unroll
        for (int j = 0; j < 8; j++)
            if (acc[j] >= 2.0f) mask3 |= 1u << (jc + j);
    }
    if (!mask3) return 0;

    float acc4[10];
    #pragma unroll
    for (int j = 0; j < 10; j++) acc4[j] = 0.0f;
    unsigned mm = mask3;
    while (mm) {
        int i = __ffs(mm) - 1; mm &= mm - 1;
        #pragma unroll
        for (int j = 0; j < 10; j++) acc4[j] += W4[j * 16 + i];
    }
    unsigned om = 0;
    #pragma unroll
    for (int j = 0; j < 10; j++)
        if (acc4[j] >= 2.0f) om |= 1u << j;
    return om;
}

#define BT  256
#define RPB 512   // 2 rows per thread: tid and tid+256

__global__ __launch_bounds__(BT)
void snn_kernel(const float* __restrict__ x,
                const float* __restrict__ W2,
                const float* __restrict__ W3,
                const float* __restrict__ W4,
                float* __restrict__ out)
{
    const int tid = threadIdx.x;
    const size_t rowbase = (size_t)blockIdx.x * RPB;
    const size_t rowA = rowbase + tid;
    const size_t rowB = rowA + 256;
    const int mp = g_minpop;

    // zero-fill this block's output tile: 1280 coalesced STG.128 (5/thread).
    {
        float4* ov = reinterpret_cast<float4*>(out + rowbase * 10);
        const float4 z = make_float4(0.f, 0.f, 0.f, 0.f);
        #pragma unroll
        for (int i = 0; i < 5; i++) ov[tid + 256 * i] = z;
    }

    // direct x reads for both rows (R8-validated path)
    const float* xa = x + rowA * 5;
    const float* xb = x + rowB * 5;
    const float a0 = __ldg(xa + 0), a1 = __ldg(xa + 1), a2 = __ldg(xa + 2),
                a3 = __ldg(xa + 3), a4 = __ldg(xa + 4);
    const float b0 = __ldg(xb + 0), b1 = __ldg(xb + 1), b2 = __ldg(xb + 2),
                b3 = __ldg(xb + 3), b4 = __ldg(xb + 4);

    // Layer 1: dense 32x5 for two rows; each uniform const load (LDCU) is
    // consumed by both rows' FMA chains. Same mul->fma order as R2/R8.
    unsigned mA = 0, mB = 0;
    #pragma unroll
    for (int o = 0; o < 32; o++) {
        const float w0 = cW1[o * 5 + 0];
        const float w1 = cW1[o * 5 + 1];
        const float w2 = cW1[o * 5 + 2];
        const float w3 = cW1[o * 5 + 3];
        const float w4 = cW1[o * 5 + 4];
        float sa = w0 * a0;
        float sb = w0 * b0;
        sa = fmaf(w1, a1, sa);  sb = fmaf(w1, b1, sb);
        sa = fmaf(w2, a2, sa);  sb = fmaf(w2, b2, sb);
        sa = fmaf(w3, a3, sa);  sb = fmaf(w3, b3, sb);
        sa = fmaf(w4, a4, sa);  sb = fmaf(w4, b4, sb);
        if (sa >= 2.0f) mA |= 1u << o;
        if (sb >= 2.0f) mB |= 1u << o;
    }

    // gate (~1e-4 taken); rare path exact. Zero-fill STGs precede in program
    // order within this thread (same thread owns both rows' output words).
    if (__popc(mA) >= mp) {
        unsigned om = rare_path(mA, W2, W3, W4);
        if (om) {
            float* o = out + rowA * 10;
            #pragma unroll
            for (int j = 0; j < 10; j++)
                o[j] = ((om >> j) & 1u) ? 1.0f : 0.0f;
        }
    }
    if (__popc(mB) >= mp) {
        unsigned om = rare_path(mB, W2, W3, W4);
        if (om) {
            float* o = out + rowB * 10;
            #pragma unroll
            for (int j = 0; j < 10; j++)
                o[j] = ((om >> j) & 1u) ? 1.0f : 0.0f;
        }
    }
}

extern "C" void kernel_launch(void* const* d_in, const int* in_sizes, int n_in,
                              void* d_out, int out_size)
{
    const float* x  = (const float*)d_in[0];
    const float* W1 = (const float*)d_in[1];
    const float* W2 = (const float*)d_in[2];
    const float* W3 = (const float*)d_in[3];
    const float* W4 = (const float*)d_in[4];
    float* out = (float*)d_out;

    const int B = in_sizes[0] / 5;        // 2097152
    const int grid = B / RPB;             // 4096

    cudaMemcpyToSymbolAsync(cW1, W1, 160 * sizeof(float), 0,
                            cudaMemcpyDeviceToDevice, 0);
    setup_kernel<<<1, 32>>>(W2);
    snn_kernel<<<grid, BT>>>(x, W2, W3, W4, out);
}